// round 14
// baseline (speedup 1.0000x reference)
#include <cuda_runtime.h>
#include <cuda_bf16.h>

// Problem constants
#define S_LEN 2048
#define HID   2048
#define NH    16
#define NKV   2
#define HD    128
#define SCALING 0.08838834764831845f

// Scratch (device globals: allocation-free rule)
__device__ float g_q[S_LEN * NH * HD];
__device__ float g_k[S_LEN * NKV * HD];
__device__ float g_v[S_LEN * NKV * HD];
__device__ float g_attn[S_LEN * NH * HD];
// tf32-prerounded copies of inputs
__device__ float g_hs[S_LEN * HID];
__device__ float g_wq[HID * NH * HD];
__device__ float g_wk[HID * NKV * HD];
__device__ float g_wv[HID * NKV * HD];
__device__ float g_wo[NH * HD * HID];

// ---------------------------------------------------------------------------
// TF32 + cp.async helpers
// ---------------------------------------------------------------------------
__device__ __forceinline__ float tf32r(float f) {
    unsigned u;
    asm("cvt.rna.tf32.f32 %0, %1;" : "=r"(u) : "f"(f));
    return __uint_as_float(u);
}

__device__ __forceinline__ void mma8(float* c,
    unsigned a0, unsigned a1, unsigned a2, unsigned a3,
    unsigned b0, unsigned b1)
{
    asm volatile(
        "mma.sync.aligned.m16n8k8.row.col.f32.tf32.tf32.f32 "
        "{%0,%1,%2,%3}, {%4,%5,%6,%7}, {%8,%9}, {%0,%1,%2,%3};\n"
        : "+f"(c[0]), "+f"(c[1]), "+f"(c[2]), "+f"(c[3])
        : "r"(a0), "r"(a1), "r"(a2), "r"(a3), "r"(b0), "r"(b1));
}

__device__ __forceinline__ void cp16(unsigned saddr, const void* gptr) {
    asm volatile("cp.async.cg.shared.global [%0], [%1], 16;\n"
                 :: "r"(saddr), "l"(gptr));
}
__device__ __forceinline__ void cp_commit() {
    asm volatile("cp.async.commit_group;\n");
}
template<int N>
__device__ __forceinline__ void cp_wait() {
    asm volatile("cp.async.wait_group %0;\n" :: "n"(N));
}

// ---------------------------------------------------------------------------
// Prepass: round hs + weights to tf32 once.
// ---------------------------------------------------------------------------
#define HS4  1048576
#define WQ4  1048576
#define WK4  131072
#define WV4  131072
#define WO4  1048576
#define TOT4 (HS4 + WQ4 + WK4 + WV4 + WO4)

__global__ void tf32_prepass_kernel(
    const float4* __restrict__ hs, const float4* __restrict__ wq,
    const float4* __restrict__ wk, const float4* __restrict__ wv,
    const float4* __restrict__ wo)
{
    int i = blockIdx.x * 256 + threadIdx.x;
    if (i >= TOT4) return;
    const float4* s; float4* d; int o;
    if (i < HS4)                         { s = hs; d = (float4*)g_hs; o = i; }
    else if (i < HS4 + WQ4)              { s = wq; d = (float4*)g_wq; o = i - HS4; }
    else if (i < HS4 + WQ4 + WK4)        { s = wk; d = (float4*)g_wk; o = i - HS4 - WQ4; }
    else if (i < HS4 + WQ4 + WK4 + WV4)  { s = wv; d = (float4*)g_wv; o = i - HS4 - WQ4 - WK4; }
    else                                 { s = wo; d = (float4*)g_wo; o = i - HS4 - WQ4 - WK4 - WV4; }
    float4 v = s[o];
    v.x = tf32r(v.x); v.y = tf32r(v.y); v.z = tf32r(v.z); v.w = tf32r(v.w);
    d[o] = v;
}

// ---------------------------------------------------------------------------
// TF32 GEMM, 3-stage cp.async pipeline (unchanged from R4).
// ---------------------------------------------------------------------------
#define G_LDA 36
#define G_LDB 136
#define G_AS_SZ (128 * G_LDA)
#define G_BS_SZ (32 * G_LDB)
#define G_STG (G_AS_SZ + G_BS_SZ)
#define G_SMEM_BYTES (3 * G_STG * 4)

__device__ __forceinline__ void gemm_tf32(
    const float* __restrict__ A, int lda,
    const float* __restrict__ B, int ldb,
    const float* __restrict__ bias,
    float* __restrict__ C, int ldc,
    int K, int m0, int n0, int round_out)
{
    extern __shared__ float smem[];
    const unsigned sbase = (unsigned)__cvta_generic_to_shared(smem);

    const int tid  = threadIdx.x;
    const int wid  = tid >> 5;
    const int lane = tid & 31;
    const int qt   = lane >> 2;
    const int qr   = lane & 3;
    const int wm   = (wid & 3) * 32;
    const int wn   = (wid >> 2) * 64;

    const int a_row = tid >> 3;
    const int a_c4  = (tid & 7) * 4;
    const int b_row = tid >> 5;
    const int b_c4  = (tid & 31) * 4;

    auto issue = [&](int s, int kk) {
#pragma unroll
        for (int f = 0; f < 4; f++) {
            int row = f * 32 + a_row;
            cp16(sbase + (unsigned)(s * G_STG + row * G_LDA + a_c4) * 4,
                 &A[(size_t)(m0 + row) * lda + kk + a_c4]);
        }
#pragma unroll
        for (int f = 0; f < 4; f++) {
            int row = f * 8 + b_row;
            cp16(sbase + (unsigned)(s * G_STG + G_AS_SZ + row * G_LDB + b_c4) * 4,
                 &B[(size_t)(kk + row) * ldb + n0 + b_c4]);
        }
        cp_commit();
    };

    float c[2][8][4];
#pragma unroll
    for (int mf = 0; mf < 2; mf++)
#pragma unroll
        for (int nf = 0; nf < 8; nf++)
#pragma unroll
            for (int e = 0; e < 4; e++) c[mf][nf][e] = 0.0f;

    const int niter = K >> 5;
    issue(0, 0);
    issue(1, 32);

    for (int i = 0; i < niter; i++) {
        cp_wait<1>();
        __syncthreads();
        const int s = i % 3;
        const float* As = smem + s * G_STG;
        const float* Bs = As + G_AS_SZ;

#pragma unroll
        for (int ks = 0; ks < 32; ks += 8) {
            unsigned a[2][4];
#pragma unroll
            for (int mf = 0; mf < 2; mf++) {
                int r = wm + mf * 16 + qt;
                a[mf][0] = __float_as_uint(As[r * G_LDA + ks + qr]);
                a[mf][1] = __float_as_uint(As[(r + 8) * G_LDA + ks + qr]);
                a[mf][2] = __float_as_uint(As[r * G_LDA + ks + qr + 4]);
                a[mf][3] = __float_as_uint(As[(r + 8) * G_LDA + ks + qr + 4]);
            }
#pragma unroll
            for (int nf = 0; nf < 8; nf++) {
                unsigned b0 = __float_as_uint(Bs[(ks + qr) * G_LDB + wn + nf * 8 + qt]);
                unsigned b1 = __float_as_uint(Bs[(ks + qr + 4) * G_LDB + wn + nf * 8 + qt]);
                mma8(c[0][nf], a[0][0], a[0][1], a[0][2], a[0][3], b0, b1);
                mma8(c[1][nf], a[1][0], a[1][1], a[1][2], a[1][3], b0, b1);
            }
        }

        int nk = i + 2;
        if (nk < niter) issue(nk % 3, nk * 32);
    }

#pragma unroll
    for (int nf = 0; nf < 8; nf++) {
        int col = n0 + wn + nf * 8 + 2 * qr;
        float b0 = bias ? bias[col]     : 0.0f;
        float b1 = bias ? bias[col + 1] : 0.0f;
#pragma unroll
        for (int mf = 0; mf < 2; mf++) {
            int r = m0 + wm + mf * 16 + qt;
            float2 v0, v1;
            v0.x = c[mf][nf][0] + b0; v0.y = c[mf][nf][1] + b1;
            v1.x = c[mf][nf][2] + b0; v1.y = c[mf][nf][3] + b1;
            if (round_out) {
                v0.x = tf32r(v0.x); v0.y = tf32r(v0.y);
                v1.x = tf32r(v1.x); v1.y = tf32r(v1.y);
            }
            *(float2*)&C[(size_t)r * ldc + col]       = v0;
            *(float2*)&C[(size_t)(r + 8) * ldc + col] = v1;
        }
    }
}

__global__ void __launch_bounds__(256, 2) qkv_gemm_kernel(
    const float* __restrict__ bq, const float* __restrict__ bk,
    const float* __restrict__ bv)
{
    int bx = blockIdx.x, by = blockIdx.y;
    const float* B; const float* bias; float* C; int ldn; int n0; int ro;
    if (bx < 16)      { B = g_wq; bias = bq; C = g_q; ldn = NH * HD;  n0 = bx * 128; ro = 0; }
    else if (bx < 18) { B = g_wk; bias = bk; C = g_k; ldn = NKV * HD; n0 = (bx - 16) * 128; ro = 0; }
    else              { B = g_wv; bias = bv; C = g_v; ldn = NKV * HD; n0 = (bx - 18) * 128; ro = 1; }
    gemm_tf32(g_hs, HID, B, ldn, bias, C, ldn, HID, by * 128, n0, ro);
}

__global__ void __launch_bounds__(256, 2) o_gemm_kernel(float* __restrict__ out)
{
    gemm_tf32(g_attn, NH * HD, g_wo, HID, nullptr, out, HID,
              NH * HD, blockIdx.y * 128, blockIdx.x * 128, 0);
}

// ---------------------------------------------------------------------------
// RoPE (in-place): rotate, scale q by SCALING, round to tf32.
// ---------------------------------------------------------------------------
__global__ void rope_kernel(const float* __restrict__ cosb,
                            const float* __restrict__ sinb)
{
    int idx = blockIdx.x * blockDim.x + threadIdx.x;
    const int QP = S_LEN * NH * 64;
    if (idx < QP) {
        int s = idx >> 10;
        int rest = idx & 1023;
        int h = rest >> 6;
        int d = rest & 63;
        float* p = g_q + (size_t)s * (NH * HD) + h * HD + d;
        float c  = cosb[s * HD + d];
        float sn = sinb[s * HD + d];
        float x0 = p[0], x1 = p[64];
        p[0]  = tf32r((x0 * c - x1 * sn) * SCALING);
        p[64] = tf32r((x1 * c + x0 * sn) * SCALING);
    } else {
        idx -= QP;
        int s = idx >> 7;
        int rest = idx & 127;
        int h = rest >> 6;
        int d = rest & 63;
        float* p = g_k + (size_t)s * (NKV * HD) + h * HD + d;
        float c  = cosb[s * HD + d];
        float sn = sinb[s * HD + d];
        float x0 = p[0], x1 = p[64];
        p[0]  = tf32r(x0 * c - x1 * sn);
        p[64] = tf32r(x1 * c + x0 * sn);
    }
}

// ---------------------------------------------------------------------------
// Flash attention v2: tf32 MMA, cp.async double-buffered K/V, P in registers
// (shuffle redistribution), no P smem.
// BM=128, BN=64, D=128, 256 threads / 8 warps; warp owns 16 rows.
// ---------------------------------------------------------------------------
#define AT_LDQ 132
#define AT_LDK 132
#define AT_LDV 136
#define AT_KSTG (64 * AT_LDK)
#define AT_VSTG (64 * AT_LDV)
#define AT_QS  0
#define AT_K0  (128 * AT_LDQ)
#define AT_V0  (AT_K0 + 2 * AT_KSTG)
#define AT_FLOATS (AT_V0 + 2 * AT_VSTG)
#define AT_SMEM_BYTES (AT_FLOATS * 4)     // 204,800 B

__global__ void __launch_bounds__(256, 1) flash_attn_kernel()
{
    extern __shared__ float sm[];
    float* Qs = sm + AT_QS;
    const unsigned sbase = (unsigned)__cvta_generic_to_shared(sm);

    const int tid  = threadIdx.x;
    const int wid  = tid >> 5;
    const int lane = tid & 31;
    const int qt   = lane >> 2;
    const int qr   = lane & 3;
    const int head = blockIdx.y;
    const int kvh  = head >> 3;
    const int qb   = 15 - blockIdx.x;
    const int r0   = qb * 128;

    const int ld_c  = tid >> 5;           // 0..7 (row base, +8 per f)
    const int ld_d4 = (tid & 31) * 4;

    // Issue cp.async for K/V tile t into stage st
    auto issue = [&](int st, int t) {
        const int k0 = t * 64;
#pragma unroll
        for (int f = 0; f < 8; f++) {
            int cc = f * 8 + ld_c;
            const float* ksrc = &g_k[(size_t)(k0 + cc) * (NKV * HD) + kvh * HD + ld_d4];
            cp16(sbase + (unsigned)(AT_K0 + st * AT_KSTG + cc * AT_LDK + ld_d4) * 4, ksrc);
            const float* vsrc = &g_v[(size_t)(k0 + cc) * (NKV * HD) + kvh * HD + ld_d4];
            cp16(sbase + (unsigned)(AT_V0 + st * AT_VSTG + cc * AT_LDV + ld_d4) * 4, vsrc);
        }
        cp_commit();
    };

    const int ntiles = 2 * qb + 2;
    issue(0, 0);

    // Load Q tile (already tf32 + scaled) — overlaps with stage-0 cp.async
#pragma unroll
    for (int f = 0; f < 16; f++) {
        int lin = f * 256 + tid;
        int row = lin >> 5;
        int c4  = (lin & 31) * 4;
        float4 v = *(const float4*)&g_q[(size_t)(r0 + row) * (NH * HD) + head * HD + c4];
        *(float4*)&Qs[row * AT_LDQ + c4] = v;
    }

    const int row_lo = wid * 16 + qt;
    const int row_hi = row_lo + 8;

    float o[16][4];
#pragma unroll
    for (int nf = 0; nf < 16; nf++)
#pragma unroll
        for (int e = 0; e < 4; e++) o[nf][e] = 0.0f;
    float m_lo = -1e30f, m_hi = -1e30f, l_lo = 0.0f, l_hi = 0.0f;

    for (int t = 0; t < ntiles; t++) {
        const int k0 = t * 64;
        const int st = t & 1;
        if (t + 1 < ntiles) {
            issue(st ^ 1, t + 1);
            cp_wait<1>();
        } else {
            cp_wait<0>();
        }
        __syncthreads();   // stage st ready; prior readers of st^1 done

        const float* Ks = sm + AT_K0 + st * AT_KSTG;
        const float* Vs = sm + AT_V0 + st * AT_VSTG;

        // ---- S = Q @ K^T ----
        float s[8][4];
#pragma unroll
        for (int nf = 0; nf < 8; nf++)
#pragma unroll
            for (int e = 0; e < 4; e++) s[nf][e] = 0.0f;

#pragma unroll
        for (int ks = 0; ks < 128; ks += 8) {
            unsigned a0 = __float_as_uint(Qs[row_lo * AT_LDQ + ks + qr]);
            unsigned a1 = __float_as_uint(Qs[row_hi * AT_LDQ + ks + qr]);
            unsigned a2 = __float_as_uint(Qs[row_lo * AT_LDQ + ks + qr + 4]);
            unsigned a3 = __float_as_uint(Qs[row_hi * AT_LDQ + ks + qr + 4]);
#pragma unroll
            for (int nf = 0; nf < 8; nf++) {
                unsigned b0 = __float_as_uint(Ks[(nf * 8 + qt) * AT_LDK + ks + qr]);
                unsigned b1 = __float_as_uint(Ks[(nf * 8 + qt) * AT_LDK + ks + qr + 4]);
                mma8(s[nf], a0, a1, a2, a3, b0, b1);
            }
        }

        // ---- causal mask + online softmax (rows warp-local) ----
        const bool need_mask = (t >= ntiles - 2);
        float mx_lo = -1e30f, mx_hi = -1e30f;
#pragma unroll
        for (int nf = 0; nf < 8; nf++) {
            if (need_mask) {
                int cg = k0 + nf * 8 + 2 * qr;
                int rg_lo = r0 + row_lo, rg_hi = r0 + row_hi;
                if (cg     > rg_lo) s[nf][0] = -1e30f;
                if (cg + 1 > rg_lo) s[nf][1] = -1e30f;
                if (cg     > rg_hi) s[nf][2] = -1e30f;
                if (cg + 1 > rg_hi) s[nf][3] = -1e30f;
            }
            mx_lo = fmaxf(mx_lo, fmaxf(s[nf][0], s[nf][1]));
            mx_hi = fmaxf(mx_hi, fmaxf(s[nf][2], s[nf][3]));
        }
        mx_lo = fmaxf(mx_lo, __shfl_xor_sync(0xffffffffu, mx_lo, 1));
        mx_lo = fmaxf(mx_lo, __shfl_xor_sync(0xffffffffu, mx_lo, 2));
        mx_hi = fmaxf(mx_hi, __shfl_xor_sync(0xffffffffu, mx_hi, 1));
        mx_hi = fmaxf(mx_hi, __shfl_xor_sync(0xffffffffu, mx_hi, 2));

        float mn_lo = fmaxf(m_lo, mx_lo);
        float mn_hi = fmaxf(m_hi, mx_hi);
        float f_lo = __expf(m_lo - mn_lo);
        float f_hi = __expf(m_hi - mn_hi);
        float sum_lo = 0.0f, sum_hi = 0.0f;
#pragma unroll
        for (int nf = 0; nf < 8; nf++) {
            float p0 = __expf(s[nf][0] - mn_lo);
            float p1 = __expf(s[nf][1] - mn_lo);
            float p2 = __expf(s[nf][2] - mn_hi);
            float p3 = __expf(s[nf][3] - mn_hi);
            sum_lo += p0 + p1;
            sum_hi += p2 + p3;
            s[nf][0] = tf32r(p0);
            s[nf][1] = tf32r(p1);
            s[nf][2] = tf32r(p2);
            s[nf][3] = tf32r(p3);
        }
        sum_lo += __shfl_xor_sync(0xffffffffu, sum_lo, 1);
        sum_lo += __shfl_xor_sync(0xffffffffu, sum_lo, 2);
        sum_hi += __shfl_xor_sync(0xffffffffu, sum_hi, 1);
        sum_hi += __shfl_xor_sync(0xffffffffu, sum_hi, 2);

        l_lo = l_lo * f_lo + sum_lo;
        l_hi = l_hi * f_hi + sum_hi;
        m_lo = mn_lo;
        m_hi = mn_hi;
#pragma unroll
        for (int nf = 0; nf < 16; nf++) {
            o[nf][0] *= f_lo; o[nf][1] *= f_lo;
            o[nf][2] *= f_hi; o[nf][3] *= f_hi;
        }

        // ---- O += P @ V : P A-frags via shuffle redistribution ----
        const int src_a = (lane & ~3) | (qr >> 1);   // qt*4 + (qr>>1)
        const int src_b = src_a + 2;
        const bool odd = qr & 1;
#pragma unroll
        for (int g = 0; g < 8; g++) {
            float x0 = __shfl_sync(0xffffffffu, s[g][0], src_a);
            float x1 = __shfl_sync(0xffffffffu, s[g][1], src_a);
            float y0 = __shfl_sync(0xffffffffu, s[g][2], src_a);
            float y1 = __shfl_sync(0xffffffffu, s[g][3], src_a);
            float z0 = __shfl_sync(0xffffffffu, s[g][0], src_b);
            float z1 = __shfl_sync(0xffffffffu, s[g][1], src_b);
            float w0 = __shfl_sync(0xffffffffu, s[g][2], src_b);
            float w1 = __shfl_sync(0xffffffffu, s[g][3], src_b);
            unsigned a0 = __float_as_uint(odd ? x1 : x0);
            unsigned a1 = __float_as_uint(odd ? y1 : y0);
            unsigned a2 = __float_as_uint(odd ? z1 : z0);
            unsigned a3 = __float_as_uint(odd ? w1 : w0);
            const int ks = g * 8;
#pragma unroll
            for (int nf = 0; nf < 16; nf++) {
                unsigned b0 = __float_as_uint(Vs[(ks + qr) * AT_LDV + nf * 8 + qt]);
                unsigned b1 = __float_as_uint(Vs[(ks + qr + 4) * AT_LDV + nf * 8 + qt]);
                mma8(o[nf], a0, a1, a2, a3, b0, b1);
            }
        }
        __syncthreads();   // readers of stage st done before t+2 overwrites it
    }

    // Epilogue: normalize, round to tf32 (o_gemm consumes directly)
    float inv_lo = 1.0f / l_lo;
    float inv_hi = 1.0f / l_hi;
#pragma unroll
    for (int nf = 0; nf < 16; nf++) {
        int col = head * HD + nf * 8 + 2 * qr;
        float2 v0, v1;
        v0.x = tf32r(o[nf][0] * inv_lo); v0.y = tf32r(o[nf][1] * inv_lo);
        v1.x = tf32r(o[nf][2] * inv_hi); v1.y = tf32r(o[nf][3] * inv_hi);
        *(float2*)&g_attn[(size_t)(r0 + row_lo) * (NH * HD) + col] = v0;
        *(float2*)&g_attn[(size_t)(r0 + row_hi) * (NH * HD) + col] = v1;
    }
}

// ---------------------------------------------------------------------------
extern "C" void kernel_launch(void* const* d_in, const int* in_sizes, int n_in,
                              void* d_out, int out_size)
{
    const float* hs   = (const float*)d_in[0];
    const float* cosb = (const float*)d_in[1];
    const float* sinb = (const float*)d_in[2];
    // d_in[3] = attention_mask (pure causal; applied analytically)
    const float* Wq = (const float*)d_in[4];
    const float* bq = (const float*)d_in[5];
    const float* Wk = (const float*)d_in[6];
    const float* bk = (const float*)d_in[7];
    const float* Wv = (const float*)d_in[8];
    const float* bv = (const float*)d_in[9];
    const float* Wo = (const float*)d_in[10];
    float* out = (float*)d_out;

    cudaFuncSetAttribute(flash_attn_kernel,
                         cudaFuncAttributeMaxDynamicSharedMemorySize, AT_SMEM_BYTES);
    cudaFuncSetAttribute(qkv_gemm_kernel,
                         cudaFuncAttributeMaxDynamicSharedMemorySize, G_SMEM_BYTES);
    cudaFuncSetAttribute(o_gemm_kernel,
                         cudaFuncAttributeMaxDynamicSharedMemorySize, G_SMEM_BYTES);

    tf32_prepass_kernel<<<(TOT4 + 255) / 256, 256>>>(
        (const float4*)hs, (const float4*)Wq, (const float4*)Wk,
        (const float4*)Wv, (const float4*)Wo);
    qkv_gemm_kernel<<<dim3(20, 16), 256, G_SMEM_BYTES>>>(bq, bk, bv);
    rope_kernel<<<(S_LEN * NH * 64 + S_LEN * NKV * 64) / 256, 256>>>(cosb, sinb);
    flash_attn_kernel<<<dim3(16, 16), 256, AT_SMEM_BYTES>>>();
    o_gemm_kernel<<<dim3(16, 16), 256, G_SMEM_BYTES>>>(out);
}

// round 16
// speedup vs baseline: 1.0484x; 1.0484x over previous
#include <cuda_runtime.h>
#include <cuda_bf16.h>

// Problem constants
#define S_LEN 2048
#define HID   2048
#define NH    16
#define NKV   2
#define HD    128
#define SCALING 0.08838834764831845f

// Scratch (device globals: allocation-free rule)
__device__ float g_q[S_LEN * NH * HD];
__device__ float g_k[S_LEN * NKV * HD];
__device__ float g_v[S_LEN * NKV * HD];
__device__ float g_attn[S_LEN * NH * HD];
// tf32-prerounded copies of inputs
__device__ float g_hs[S_LEN * HID];
__device__ float g_wq[HID * NH * HD];
__device__ float g_wk[HID * NKV * HD];
__device__ float g_wv[HID * NKV * HD];
__device__ float g_wo[NH * HD * HID];

// ---------------------------------------------------------------------------
// TF32 + cp.async helpers
// ---------------------------------------------------------------------------
__device__ __forceinline__ float tf32r(float f) {
    unsigned u;
    asm("cvt.rna.tf32.f32 %0, %1;" : "=r"(u) : "f"(f));
    return __uint_as_float(u);
}

__device__ __forceinline__ void mma8(float* c,
    unsigned a0, unsigned a1, unsigned a2, unsigned a3,
    unsigned b0, unsigned b1)
{
    asm volatile(
        "mma.sync.aligned.m16n8k8.row.col.f32.tf32.tf32.f32 "
        "{%0,%1,%2,%3}, {%4,%5,%6,%7}, {%8,%9}, {%0,%1,%2,%3};\n"
        : "+f"(c[0]), "+f"(c[1]), "+f"(c[2]), "+f"(c[3])
        : "r"(a0), "r"(a1), "r"(a2), "r"(a3), "r"(b0), "r"(b1));
}

__device__ __forceinline__ void cp16(unsigned saddr, const void* gptr) {
    asm volatile("cp.async.cg.shared.global [%0], [%1], 16;\n"
                 :: "r"(saddr), "l"(gptr));
}
__device__ __forceinline__ void cp_commit() {
    asm volatile("cp.async.commit_group;\n");
}
template<int N>
__device__ __forceinline__ void cp_wait() {
    asm volatile("cp.async.wait_group %0;\n" :: "n"(N));
}

// ---------------------------------------------------------------------------
// Prepass: round hs + weights to tf32 once. (unchanged)
// ---------------------------------------------------------------------------
#define HS4  1048576
#define WQ4  1048576
#define WK4  131072
#define WV4  131072
#define WO4  1048576
#define TOT4 (HS4 + WQ4 + WK4 + WV4 + WO4)

__global__ void tf32_prepass_kernel(
    const float4* __restrict__ hs, const float4* __restrict__ wq,
    const float4* __restrict__ wk, const float4* __restrict__ wv,
    const float4* __restrict__ wo)
{
    int i = blockIdx.x * 256 + threadIdx.x;
    if (i >= TOT4) return;
    const float4* s; float4* d; int o;
    if (i < HS4)                         { s = hs; d = (float4*)g_hs; o = i; }
    else if (i < HS4 + WQ4)              { s = wq; d = (float4*)g_wq; o = i - HS4; }
    else if (i < HS4 + WQ4 + WK4)        { s = wk; d = (float4*)g_wk; o = i - HS4 - WQ4; }
    else if (i < HS4 + WQ4 + WK4 + WV4)  { s = wv; d = (float4*)g_wv; o = i - HS4 - WQ4 - WK4; }
    else                                 { s = wo; d = (float4*)g_wo; o = i - HS4 - WQ4 - WK4 - WV4; }
    float4 v = s[o];
    v.x = tf32r(v.x); v.y = tf32r(v.y); v.z = tf32r(v.z); v.w = tf32r(v.w);
    d[o] = v;
}

// ---------------------------------------------------------------------------
// TF32 GEMM, 3-stage cp.async pipeline (unchanged — part of banked build).
// ---------------------------------------------------------------------------
#define G_LDA 36
#define G_LDB 136
#define G_AS_SZ (128 * G_LDA)
#define G_BS_SZ (32 * G_LDB)
#define G_STG (G_AS_SZ + G_BS_SZ)
#define G_SMEM_BYTES (3 * G_STG * 4)

__device__ __forceinline__ void gemm_tf32(
    const float* __restrict__ A, int lda,
    const float* __restrict__ B, int ldb,
    const float* __restrict__ bias,
    float* __restrict__ C, int ldc,
    int K, int m0, int n0, int round_out)
{
    extern __shared__ float smem[];
    const unsigned sbase = (unsigned)__cvta_generic_to_shared(smem);

    const int tid  = threadIdx.x;
    const int wid  = tid >> 5;
    const int lane = tid & 31;
    const int qt   = lane >> 2;
    const int qr   = lane & 3;
    const int wm   = (wid & 3) * 32;
    const int wn   = (wid >> 2) * 64;

    const int a_row = tid >> 3;
    const int a_c4  = (tid & 7) * 4;
    const int b_row = tid >> 5;
    const int b_c4  = (tid & 31) * 4;

    auto issue = [&](int s, int kk) {
#pragma unroll
        for (int f = 0; f < 4; f++) {
            int row = f * 32 + a_row;
            cp16(sbase + (unsigned)(s * G_STG + row * G_LDA + a_c4) * 4,
                 &A[(size_t)(m0 + row) * lda + kk + a_c4]);
        }
#pragma unroll
        for (int f = 0; f < 4; f++) {
            int row = f * 8 + b_row;
            cp16(sbase + (unsigned)(s * G_STG + G_AS_SZ + row * G_LDB + b_c4) * 4,
                 &B[(size_t)(kk + row) * ldb + n0 + b_c4]);
        }
        cp_commit();
    };

    float c[2][8][4];
#pragma unroll
    for (int mf = 0; mf < 2; mf++)
#pragma unroll
        for (int nf = 0; nf < 8; nf++)
#pragma unroll
            for (int e = 0; e < 4; e++) c[mf][nf][e] = 0.0f;

    const int niter = K >> 5;
    issue(0, 0);
    issue(1, 32);

    for (int i = 0; i < niter; i++) {
        cp_wait<1>();
        __syncthreads();
        const int s = i % 3;
        const float* As = smem + s * G_STG;
        const float* Bs = As + G_AS_SZ;

#pragma unroll
        for (int ks = 0; ks < 32; ks += 8) {
            unsigned a[2][4];
#pragma unroll
            for (int mf = 0; mf < 2; mf++) {
                int r = wm + mf * 16 + qt;
                a[mf][0] = __float_as_uint(As[r * G_LDA + ks + qr]);
                a[mf][1] = __float_as_uint(As[(r + 8) * G_LDA + ks + qr]);
                a[mf][2] = __float_as_uint(As[r * G_LDA + ks + qr + 4]);
                a[mf][3] = __float_as_uint(As[(r + 8) * G_LDA + ks + qr + 4]);
            }
#pragma unroll
            for (int nf = 0; nf < 8; nf++) {
                unsigned b0 = __float_as_uint(Bs[(ks + qr) * G_LDB + wn + nf * 8 + qt]);
                unsigned b1 = __float_as_uint(Bs[(ks + qr + 4) * G_LDB + wn + nf * 8 + qt]);
                mma8(c[0][nf], a[0][0], a[0][1], a[0][2], a[0][3], b0, b1);
                mma8(c[1][nf], a[1][0], a[1][1], a[1][2], a[1][3], b0, b1);
            }
        }

        int nk = i + 2;
        if (nk < niter) issue(nk % 3, nk * 32);
    }

#pragma unroll
    for (int nf = 0; nf < 8; nf++) {
        int col = n0 + wn + nf * 8 + 2 * qr;
        float b0 = bias ? bias[col]     : 0.0f;
        float b1 = bias ? bias[col + 1] : 0.0f;
#pragma unroll
        for (int mf = 0; mf < 2; mf++) {
            int r = m0 + wm + mf * 16 + qt;
            float2 v0, v1;
            v0.x = c[mf][nf][0] + b0; v0.y = c[mf][nf][1] + b1;
            v1.x = c[mf][nf][2] + b0; v1.y = c[mf][nf][3] + b1;
            if (round_out) {
                v0.x = tf32r(v0.x); v0.y = tf32r(v0.y);
                v1.x = tf32r(v1.x); v1.y = tf32r(v1.y);
            }
            *(float2*)&C[(size_t)r * ldc + col]       = v0;
            *(float2*)&C[(size_t)(r + 8) * ldc + col] = v1;
        }
    }
}

__global__ void __launch_bounds__(256, 2) qkv_gemm_kernel(
    const float* __restrict__ bq, const float* __restrict__ bk,
    const float* __restrict__ bv)
{
    int bx = blockIdx.x, by = blockIdx.y;
    const float* B; const float* bias; float* C; int ldn; int n0; int ro;
    if (bx < 16)      { B = g_wq; bias = bq; C = g_q; ldn = NH * HD;  n0 = bx * 128; ro = 0; }
    else if (bx < 18) { B = g_wk; bias = bk; C = g_k; ldn = NKV * HD; n0 = (bx - 16) * 128; ro = 0; }
    else              { B = g_wv; bias = bv; C = g_v; ldn = NKV * HD; n0 = (bx - 18) * 128; ro = 1; }
    gemm_tf32(g_hs, HID, B, ldn, bias, C, ldn, HID, by * 128, n0, ro);
}

__global__ void __launch_bounds__(256, 2) o_gemm_kernel(float* __restrict__ out)
{
    gemm_tf32(g_attn, NH * HD, g_wo, HID, nullptr, out, HID,
              NH * HD, blockIdx.y * 128, blockIdx.x * 128, 0);
}

// ---------------------------------------------------------------------------
// RoPE (in-place): rotate, scale q by SCALING, round to tf32. (unchanged)
// ---------------------------------------------------------------------------
__global__ void rope_kernel(const float* __restrict__ cosb,
                            const float* __restrict__ sinb)
{
    int idx = blockIdx.x * blockDim.x + threadIdx.x;
    const int QP = S_LEN * NH * 64;
    if (idx < QP) {
        int s = idx >> 10;
        int rest = idx & 1023;
        int h = rest >> 6;
        int d = rest & 63;
        float* p = g_q + (size_t)s * (NH * HD) + h * HD + d;
        float c  = cosb[s * HD + d];
        float sn = sinb[s * HD + d];
        float x0 = p[0], x1 = p[64];
        p[0]  = tf32r((x0 * c - x1 * sn) * SCALING);
        p[64] = tf32r((x1 * c + x0 * sn) * SCALING);
    } else {
        idx -= QP;
        int s = idx >> 7;
        int rest = idx & 127;
        int h = rest >> 6;
        int d = rest & 63;
        float* p = g_k + (size_t)s * (NKV * HD) + h * HD + d;
        float c  = cosb[s * HD + d];
        float sn = sinb[s * HD + d];
        float x0 = p[0], x1 = p[64];
        p[0]  = tf32r(x0 * c - x1 * sn);
        p[64] = tf32r(x1 * c + x0 * sn);
    }
}

// ---------------------------------------------------------------------------
// Flash attention v4: BM=64, 128 threads / 4 warps, 2 CTAs per SM,
// Q pre-staged in REGISTERS (a-fragments), K/V single-buffer cp.async.
// Per-warp math (16 rows x 64 cols, op order) identical to the banked v2 ->
// per-row bitwise-identical output (dropped tiles were exact no-ops).
// Causal: ntiles = qb+1, mask only the diagonal tile.
// ---------------------------------------------------------------------------
#define AT_LDK 132
#define AT_LDV 136
#define AT_KS  0
#define AT_VS  (64 * AT_LDK)
#define AT_FLOATS (AT_VS + 64 * AT_LDV)
#define AT_SMEM_BYTES (AT_FLOATS * 4)     // 68,608 B -> 2 CTAs/SM

__global__ void __launch_bounds__(128, 2) flash_attn_kernel()
{
    extern __shared__ float sm[];
    float* Ks = sm + AT_KS;
    float* Vs = sm + AT_VS;
    const unsigned sbase = (unsigned)__cvta_generic_to_shared(sm);

    const int tid  = threadIdx.x;
    const int wid  = tid >> 5;            // 0..3
    const int lane = tid & 31;
    const int qt   = lane >> 2;
    const int qr   = lane & 3;
    const int head = blockIdx.y;
    const int kvh  = head >> 3;           // N_REP = 8
    const int qb   = 31 - blockIdx.x;     // big blocks first
    const int r0   = qb * 64;

    const int ld_c  = tid >> 5;           // 0..3 (row base, +4 per f)
    const int ld_d4 = (tid & 31) * 4;

    // Issue cp.async for K/V tile t (single buffer)
    auto issue = [&](int t) {
        const int k0 = t * 64;
#pragma unroll
        for (int f = 0; f < 16; f++) {
            int cc = f * 4 + ld_c;
            const float* ksrc = &g_k[(size_t)(k0 + cc) * (NKV * HD) + kvh * HD + ld_d4];
            cp16(sbase + (unsigned)(AT_KS + cc * AT_LDK + ld_d4) * 4, ksrc);
            const float* vsrc = &g_v[(size_t)(k0 + cc) * (NKV * HD) + kvh * HD + ld_d4];
            cp16(sbase + (unsigned)(AT_VS + cc * AT_LDV + ld_d4) * 4, vsrc);
        }
        cp_commit();
    };

    issue(0);

    const int row_lo = wid * 16 + qt;
    const int row_hi = row_lo + 8;

    // Pre-stage Q a-fragments in registers (same tf32 bits as smem path fed
    // to the same MMA sequence -> identical results). 64 regs.
    unsigned qa[16][4];
    {
        const float* qlo = &g_q[(size_t)(r0 + row_lo) * (NH * HD) + head * HD];
        const float* qhi = &g_q[(size_t)(r0 + row_hi) * (NH * HD) + head * HD];
#pragma unroll
        for (int g = 0; g < 16; g++) {
            qa[g][0] = __float_as_uint(qlo[g * 8 + qr]);
            qa[g][1] = __float_as_uint(qhi[g * 8 + qr]);
            qa[g][2] = __float_as_uint(qlo[g * 8 + qr + 4]);
            qa[g][3] = __float_as_uint(qhi[g * 8 + qr + 4]);
        }
    }

    float o[16][4];
#pragma unroll
    for (int nf = 0; nf < 16; nf++)
#pragma unroll
        for (int e = 0; e < 4; e++) o[nf][e] = 0.0f;
    float m_lo = -1e30f, m_hi = -1e30f, l_lo = 0.0f, l_hi = 0.0f;

    const int ntiles = qb + 1;
    for (int t = 0; t < ntiles; t++) {
        const int k0 = t * 64;
        cp_wait<0>();
        __syncthreads();   // K/V tile visible to all warps

        // ---- S = Q @ K^T ----
        float s[8][4];
#pragma unroll
        for (int nf = 0; nf < 8; nf++)
#pragma unroll
            for (int e = 0; e < 4; e++) s[nf][e] = 0.0f;

#pragma unroll
        for (int g = 0; g < 16; g++) {
            const int ks = g * 8;
#pragma unroll
            for (int nf = 0; nf < 8; nf++) {
                unsigned b0 = __float_as_uint(Ks[(nf * 8 + qt) * AT_LDK + ks + qr]);
                unsigned b1 = __float_as_uint(Ks[(nf * 8 + qt) * AT_LDK + ks + qr + 4]);
                mma8(s[nf], qa[g][0], qa[g][1], qa[g][2], qa[g][3], b0, b1);
            }
        }

        // ---- causal mask + online softmax (rows warp-local) ----
        const bool need_mask = (t == ntiles - 1);
        float mx_lo = -1e30f, mx_hi = -1e30f;
#pragma unroll
        for (int nf = 0; nf < 8; nf++) {
            if (need_mask) {
                int cg = k0 + nf * 8 + 2 * qr;
                int rg_lo = r0 + row_lo, rg_hi = r0 + row_hi;
                if (cg     > rg_lo) s[nf][0] = -1e30f;
                if (cg + 1 > rg_lo) s[nf][1] = -1e30f;
                if (cg     > rg_hi) s[nf][2] = -1e30f;
                if (cg + 1 > rg_hi) s[nf][3] = -1e30f;
            }
            mx_lo = fmaxf(mx_lo, fmaxf(s[nf][0], s[nf][1]));
            mx_hi = fmaxf(mx_hi, fmaxf(s[nf][2], s[nf][3]));
        }
        mx_lo = fmaxf(mx_lo, __shfl_xor_sync(0xffffffffu, mx_lo, 1));
        mx_lo = fmaxf(mx_lo, __shfl_xor_sync(0xffffffffu, mx_lo, 2));
        mx_hi = fmaxf(mx_hi, __shfl_xor_sync(0xffffffffu, mx_hi, 1));
        mx_hi = fmaxf(mx_hi, __shfl_xor_sync(0xffffffffu, mx_hi, 2));

        float mn_lo = fmaxf(m_lo, mx_lo);
        float mn_hi = fmaxf(m_hi, mx_hi);
        float f_lo = __expf(m_lo - mn_lo);
        float f_hi = __expf(m_hi - mn_hi);
        float sum_lo = 0.0f, sum_hi = 0.0f;
#pragma unroll
        for (int nf = 0; nf < 8; nf++) {
            float p0 = __expf(s[nf][0] - mn_lo);
            float p1 = __expf(s[nf][1] - mn_lo);
            float p2 = __expf(s[nf][2] - mn_hi);
            float p3 = __expf(s[nf][3] - mn_hi);
            sum_lo += p0 + p1;
            sum_hi += p2 + p3;
            s[nf][0] = tf32r(p0);
            s[nf][1] = tf32r(p1);
            s[nf][2] = tf32r(p2);
            s[nf][3] = tf32r(p3);
        }
        sum_lo += __shfl_xor_sync(0xffffffffu, sum_lo, 1);
        sum_lo += __shfl_xor_sync(0xffffffffu, sum_lo, 2);
        sum_hi += __shfl_xor_sync(0xffffffffu, sum_hi, 1);
        sum_hi += __shfl_xor_sync(0xffffffffu, sum_hi, 2);

        l_lo = l_lo * f_lo + sum_lo;
        l_hi = l_hi * f_hi + sum_hi;
        m_lo = mn_lo;
        m_hi = mn_hi;
#pragma unroll
        for (int nf = 0; nf < 16; nf++) {
            o[nf][0] *= f_lo; o[nf][1] *= f_lo;
            o[nf][2] *= f_hi; o[nf][3] *= f_hi;
        }

        // ---- O += P @ V : P A-frags via shuffle redistribution ----
        const int src_a = (lane & ~3) | (qr >> 1);   // qt*4 + (qr>>1)
        const int src_b = src_a + 2;
        const bool odd = qr & 1;
#pragma unroll
        for (int g = 0; g < 8; g++) {
            float x0 = __shfl_sync(0xffffffffu, s[g][0], src_a);
            float x1 = __shfl_sync(0xffffffffu, s[g][1], src_a);
            float y0 = __shfl_sync(0xffffffffu, s[g][2], src_a);
            float y1 = __shfl_sync(0xffffffffu, s[g][3], src_a);
            float z0 = __shfl_sync(0xffffffffu, s[g][0], src_b);
            float z1 = __shfl_sync(0xffffffffu, s[g][1], src_b);
            float w0 = __shfl_sync(0xffffffffu, s[g][2], src_b);
            float w1 = __shfl_sync(0xffffffffu, s[g][3], src_b);
            unsigned a0 = __float_as_uint(odd ? x1 : x0);
            unsigned a1 = __float_as_uint(odd ? y1 : y0);
            unsigned a2 = __float_as_uint(odd ? z1 : z0);
            unsigned a3 = __float_as_uint(odd ? w1 : w0);
            const int ks = g * 8;
#pragma unroll
            for (int nf = 0; nf < 16; nf++) {
                unsigned b0 = __float_as_uint(Vs[(ks + qr) * AT_LDV + nf * 8 + qt]);
                unsigned b1 = __float_as_uint(Vs[(ks + qr + 4) * AT_LDV + nf * 8 + qt]);
                mma8(o[nf], a0, a1, a2, a3, b0, b1);
            }
        }

        if (t + 1 < ntiles) {
            __syncthreads();   // all readers of K/V done before overwrite
            issue(t + 1);
        }
    }

    // Epilogue: normalize, round to tf32 (o_gemm consumes directly)
    float inv_lo = 1.0f / l_lo;
    float inv_hi = 1.0f / l_hi;
#pragma unroll
    for (int nf = 0; nf < 16; nf++) {
        int col = head * HD + nf * 8 + 2 * qr;
        float2 v0, v1;
        v0.x = tf32r(o[nf][0] * inv_lo); v0.y = tf32r(o[nf][1] * inv_lo);
        v1.x = tf32r(o[nf][2] * inv_hi); v1.y = tf32r(o[nf][3] * inv_hi);
        *(float2*)&g_attn[(size_t)(r0 + row_lo) * (NH * HD) + col] = v0;
        *(float2*)&g_attn[(size_t)(r0 + row_hi) * (NH * HD) + col] = v1;
    }
}

// ---------------------------------------------------------------------------
extern "C" void kernel_launch(void* const* d_in, const int* in_sizes, int n_in,
                              void* d_out, int out_size)
{
    const float* hs   = (const float*)d_in[0];
    const float* cosb = (const float*)d_in[1];
    const float* sinb = (const float*)d_in[2];
    // d_in[3] = attention_mask (pure causal; applied analytically)
    const float* Wq = (const float*)d_in[4];
    const float* bq = (const float*)d_in[5];
    const float* Wk = (const float*)d_in[6];
    const float* bk = (const float*)d_in[7];
    const float* Wv = (const float*)d_in[8];
    const float* bv = (const float*)d_in[9];
    const float* Wo = (const float*)d_in[10];
    float* out = (float*)d_out;

    cudaFuncSetAttribute(flash_attn_kernel,
                         cudaFuncAttributeMaxDynamicSharedMemorySize, AT_SMEM_BYTES);
    cudaFuncSetAttribute(qkv_gemm_kernel,
                         cudaFuncAttributeMaxDynamicSharedMemorySize, G_SMEM_BYTES);
    cudaFuncSetAttribute(o_gemm_kernel,
                         cudaFuncAttributeMaxDynamicSharedMemorySize, G_SMEM_BYTES);

    tf32_prepass_kernel<<<(TOT4 + 255) / 256, 256>>>(
        (const float4*)hs, (const float4*)Wq, (const float4*)Wk,
        (const float4*)Wv, (const float4*)Wo);
    qkv_gemm_kernel<<<dim3(20, 16), 256, G_SMEM_BYTES>>>(bq, bk, bv);
    rope_kernel<<<(S_LEN * NH * 64 + S_LEN * NKV * 64) / 256, 256>>>(cosb, sinb);
    flash_attn_kernel<<<dim3(32, 16), 128, AT_SMEM_BYTES>>>();
    o_gemm_kernel<<<dim3(16, 16), 256, G_SMEM_BYTES>>>(out);
}